// round 1
// baseline (speedup 1.0000x reference)
#include <cuda_runtime.h>
#include <math.h>

#define CH   128
#define SP   8192                 // 8*32*32 spatial per (n, c)
#define TSZ  2097152              // B*CH*SP = 2*128*8192 (one t-slice)
#define TOT  8388608              // 4*TSZ

// ---------------- device scratch (static: allocation-free) ----------------
__device__ float g_wT[27*CH*CH];      // folded conv weights, [tap][i][o]
__device__ float g_kwT[CH*CH];        // [i][o]
__device__ float g_pwT[CH*CH];        // [i][o]
__device__ float g_qraw[TOT];
__device__ float g_kraw[TOT];
__device__ float g_qs[TOT];
__device__ float g_ks[TOT];
__device__ float g_vs[TOT];
__device__ float g_attno[TOT];
__device__ float g_souts[TOT];
__device__ float g_pwraw[TOT];
__device__ float g_scale[4*CH];
__device__ float g_shift[4*CH];
__device__ float g_qreg[16*CH];       // [b][w][c]
__device__ float g_kreg[16*CH];
__device__ int   g_topk[64];          // [b][w][4]

// ---------------- weight prep ----------------
// cdc_t folding: out = conv3d(x, w) - theta * (kd @ x), kd = sum over hw of
// temporal slices dz=0 and dz=2.  Equivalent to subtracting theta*kd from the
// center tap (dz=dy=dx=1 -> tap 13).  Output layout [tap][i][o] for coalesced
// GEMM A-loads.
__global__ void fold_kernel(const float* __restrict__ qw, float* __restrict__ wT) {
    int o = blockIdx.x, i = threadIdx.x;
    const float* wp = qw + (o*CH + i)*27;
    float kd = 0.f;
#pragma unroll
    for (int j = 0; j < 9; j++) kd += wp[j] + wp[18+j];
#pragma unroll
    for (int tap = 0; tap < 27; tap++) {
        float v = wp[tap];
        if (tap == 13) v -= 0.7f * kd;
        wT[(tap*CH + i)*CH + o] = v;
    }
}

__global__ void transpose_kernel(const float* __restrict__ src, float* __restrict__ dst) {
    int o = blockIdx.x, i = threadIdx.x;
    dst[i*CH + o] = src[o*CH + i];
}

// ---------------- generic implicit-GEMM conv / channel matmul ----------------
// out[n,o,z,y,x] = sum_{tap,i} wT[tap][i][o] * in[n,i,z+dz,y+dy,x+dx]  (zero pad)
// ntaps==27: 3x3x3 conv (dz,dy,dx from tap, offsets -1..1). ntaps==1: 1x1x1.
// CTA tile: M=128 (all o) x N=128 spatial (4 y-rows x 32 x) at fixed (n,z).
// grid 512 = n(8) * z(8) * ygroup(8); 256 threads, 8x8 register tile.
__global__ __launch_bounds__(256, 2) void gemm_conv(
    const float* __restrict__ in, const float* __restrict__ wT,
    float* __restrict__ out, int ntaps)
{
    __shared__ float As[16][128];
    __shared__ float Bs[16][128];
    int blk = blockIdx.x;
    int n = blk >> 6, z = (blk >> 3) & 7, y0 = (blk & 7) << 2;
    int tid = threadIdx.x;
    int rg = tid >> 4, cg = tid & 15;

    float acc[8][8];
#pragma unroll
    for (int r = 0; r < 8; r++)
#pragma unroll
        for (int c = 0; c < 8; c++) acc[r][c] = 0.f;

    const float* inb = in + (long)n*CH*SP;
    int nch = ntaps << 3;   // 8 i-chunks of 16 per tap

    for (int ch = 0; ch < nch; ch++) {
        int tap = ch >> 3, i0 = (ch & 7) << 4;
        int dz = 0, dy = 0, dx = 0;
        if (ntaps == 27) {
            dz = tap/9 - 1;
            int r9 = tap - (tap/9)*9;
            dy = r9/3 - 1;
            dx = r9 - (r9/3)*3 - 1;
        }
        // A: [kk][o], contiguous in o
#pragma unroll
        for (int j = 0; j < 8; j++) {
            int e = j*256 + tid, kk = e >> 7, o = e & 127;
            As[kk][o] = wT[(tap*CH + i0 + kk)*CH + o];
        }
        // B: [kk][s], s = ly*32+lx, shifted input with zero padding
        int iz = z + dz;
        bool zok = ((unsigned)iz < 8u);
#pragma unroll
        for (int j = 0; j < 8; j++) {
            int e = j*256 + tid, kk = e >> 7, ss = e & 127;
            int ly = ss >> 5, lx = ss & 31;
            int iy = y0 + ly + dy, ix = lx + dx;
            float v = 0.f;
            if (zok && (unsigned)iy < 32u && (unsigned)ix < 32u)
                v = inb[(i0+kk)*SP + iz*1024 + iy*32 + ix];
            Bs[kk][ss] = v;
        }
        __syncthreads();
#pragma unroll
        for (int kk = 0; kk < 16; kk++) {
            const float4* A4 = reinterpret_cast<const float4*>(&As[kk][0]);
            const float4* B4 = reinterpret_cast<const float4*>(&Bs[kk][0]);
            float4 a0 = A4[rg*2], a1 = A4[rg*2+1];
            float4 b0 = B4[cg*2], b1 = B4[cg*2+1];
            float a[8] = {a0.x,a0.y,a0.z,a0.w,a1.x,a1.y,a1.z,a1.w};
            float b[8] = {b0.x,b0.y,b0.z,b0.w,b1.x,b1.y,b1.z,b1.w};
#pragma unroll
            for (int r = 0; r < 8; r++)
#pragma unroll
                for (int c = 0; c < 8; c++)
                    acc[r][c] += a[r]*b[c];
        }
        __syncthreads();
    }
#pragma unroll
    for (int r = 0; r < 8; r++) {
        int o = rg*8 + r;
        float* op = out + (((long)n*CH + o)*8 + z)*1024 + y0*32 + cg*8;
        *reinterpret_cast<float4*>(op)   = make_float4(acc[r][0],acc[r][1],acc[r][2],acc[r][3]);
        *reinterpret_cast<float4*>(op+4) = make_float4(acc[r][4],acc[r][5],acc[r][6],acc[r][7]);
    }
}

// ---------------- per-channel batch stats (fp64 accum) ----------------
__global__ void stats_kernel(const float* __restrict__ in,
                             const float* __restrict__ gamma, const float* __restrict__ beta,
                             float* __restrict__ scale, float* __restrict__ shift)
{
    int c = blockIdx.x, tid = threadIdx.x;
    double s = 0.0, s2 = 0.0;
    for (int e = tid; e < 65536; e += 256) {
        float v = in[(long)(e>>13)*(CH*SP) + (long)c*SP + (e & (SP-1))];
        s += v; s2 += (double)v*(double)v;
    }
    __shared__ double sh1[256], sh2[256];
    sh1[tid] = s; sh2[tid] = s2;
    __syncthreads();
    for (int m = 128; m > 0; m >>= 1) {
        if (tid < m) { sh1[tid] += sh1[tid+m]; sh2[tid] += sh2[tid+m]; }
        __syncthreads();
    }
    if (tid == 0) {
        double mean = sh1[0] / 65536.0;
        double var  = sh2[0] / 65536.0 - mean*mean;
        float sc = gamma[c] * (float)(1.0/sqrt(var + 1e-5));
        scale[c] = sc;
        shift[c] = beta[c] - (float)mean * sc;
    }
}

// ---------------- window region means (affined) ----------------
// reg[b][w][c] = mean over (t, window positions) of BN'd value
__global__ void region_kernel(const float* __restrict__ raw,
                              const float* __restrict__ scale, const float* __restrict__ shift,
                              float* __restrict__ reg)
{
    int blk = blockIdx.x;                 // 2048 = b*1024 + w*128 + c
    int c = blk & 127, w = (blk >> 7) & 7, b = blk >> 10;
    int wz = w >> 2, wy = (w >> 1) & 1, wx = w & 1;
    int tid = threadIdx.x;                // 128
    double sum = 0.0;
    for (int e = tid; e < 4096; e += 128) {
        int t = e >> 10, r = e & 1023;
        int sz = r >> 8, sy = (r >> 4) & 15, sx = r & 15;
        int pos = (wz*4+sz)*1024 + (wy*16+sy)*32 + (wx*16+sx);
        sum += raw[((long)(t*2+b)*CH + c)*SP + pos];
    }
    __shared__ double sh[128];
    sh[tid] = sum; __syncthreads();
    for (int m = 64; m > 0; m >>= 1) {
        if (tid < m) sh[tid] += sh[tid+m];
        __syncthreads();
    }
    if (tid == 0)
        reg[(b*8+w)*CH + c] = (float)(sh[0] / 4096.0) * scale[c] + shift[c];
}

// ---------------- routing: a_r + top-4 ----------------
__global__ void route_kernel() {
    int tid = threadIdx.x;
    __shared__ float ar[128];             // [b][w][v]
    if (tid < 128) {
        int b = tid >> 6, w = (tid >> 3) & 7, v = tid & 7;
        float s = 0.f;
        for (int c = 0; c < 128; c++)
            s += g_qreg[(b*8+w)*CH+c] * g_kreg[(b*8+v)*CH+c];
        ar[tid] = s * 0.25f;              // HEAD_DIM^-0.5 (ordering-invariant anyway)
    }
    __syncthreads();
    if (tid < 16) {                       // tid = b*8 + w
        int base = tid * 8;
        bool used[8] = {false,false,false,false,false,false,false,false};
        for (int j = 0; j < 4; j++) {
            int best = 0; float bv = -1e30f;
            for (int v = 0; v < 8; v++)
                if (!used[v] && ar[base+v] > bv) { bv = ar[base+v]; best = v; }
            used[best] = true;
            g_topk[tid*4 + j] = best;     // ties -> lowest index, matches lax.top_k
        }
    }
}

// ---------------- BN (optional) + LIF over T ----------------
__global__ void lif_kernel(const float* __restrict__ raw,
                           const float* __restrict__ scale, const float* __restrict__ shift,
                           float* __restrict__ sp)
{
    int i = blockIdx.x*256 + threadIdx.x;     // [0, TSZ)
    float sc = 1.f, sh = 0.f;
    if (scale) { int c = (i >> 13) & 127; sc = scale[c]; sh = shift[c]; }
    float v = 0.f;
#pragma unroll
    for (int t = 0; t < 4; t++) {
        float u = raw[(long)t*TSZ + i]*sc + sh;
        v = v + (u - v)*0.5f;                 // v += (x - v)/tau, tau=2 (exact halving)
        float s = (v >= 1.0f) ? 1.f : 0.f;    // spike(v - V_TH)
        sp[(long)t*TSZ + i] = s;
        v *= (1.f - s);                       // hard reset
    }
}

// ---------------- attention: gather top-k windows, dot over head dim, LIF, *v ----------------
// thread per (b, w, s, c); 16-lane shfl reduction per head (c = h*16 + d).
// All values are small dyadic rationals -> bit-exact vs reference given same spikes.
__global__ void attn_kernel() {
    int i = blockIdx.x*256 + threadIdx.x;     // [0, TSZ)
    int c = i & 127;
    int s = (i >> 7) & 1023;
    int w = (i >> 17) & 7;
    int b = i >> 20;
    int sz = s >> 8, sy = (s >> 4) & 15, sx = s & 15;
    int pos = ((w>>2)*4+sz)*1024 + (((w>>1)&1)*16+sy)*32 + ((w&1)*16+sx);
    const int* tk = &g_topk[(b*8+w)*4];
    int pj[4];
#pragma unroll
    for (int j = 0; j < 4; j++) {
        int wj = tk[j];
        pj[j] = ((wj>>2)*4+sz)*1024 + (((wj>>1)&1)*16+sy)*32 + ((wj&1)*16+sx);
    }
    float vmem = 0.f;
#pragma unroll
    for (int t = 0; t < 4; t++) {
        long base = ((long)(t*2+b)*CH + c)*SP;
        float q = g_qs[base + pos];
        float kk = g_ks[base+pj[0]] + g_ks[base+pj[1]] + g_ks[base+pj[2]] + g_ks[base+pj[3]];
        float p = q * kk;
        p += __shfl_xor_sync(0xffffffffu, p, 1);
        p += __shfl_xor_sync(0xffffffffu, p, 2);
        p += __shfl_xor_sync(0xffffffffu, p, 4);
        p += __shfl_xor_sync(0xffffffffu, p, 8);
        float a = p * 0.25f;                  // q . mean_j(k)
        vmem = vmem + (a - vmem)*0.5f;        // LIF on attn logits
        float spk = (vmem >= 1.0f) ? 1.f : 0.f;
        vmem *= (1.f - spk);
        float vv = g_vs[base+pj[0]] + g_vs[base+pj[1]] + g_vs[base+pj[2]] + g_vs[base+pj[3]];
        g_attno[base + pos] = spk * vv * 0.25f;
    }
}

// ---------------- final affine (BN apply) ----------------
__global__ void affine_kernel(const float* __restrict__ raw,
                              const float* __restrict__ scale, const float* __restrict__ shift,
                              float* __restrict__ out)
{
    int i = blockIdx.x*256 + threadIdx.x;
    int c = (i >> 13) & 127;
    out[i] = raw[i]*scale[c] + shift[c];
}

// ---------------- host ----------------
extern "C" void kernel_launch(void* const* d_in, const int* in_sizes, int n_in,
                              void* d_out, int out_size)
{
    const float* x  = (const float*)d_in[0];
    const float* qw = (const float*)d_in[1];
    const float* qg = (const float*)d_in[2];
    const float* qb = (const float*)d_in[3];
    const float* kw = (const float*)d_in[4];
    const float* kg = (const float*)d_in[5];
    const float* kb = (const float*)d_in[6];
    const float* vg = (const float*)d_in[7];
    const float* vb = (const float*)d_in[8];
    const float* pw = (const float*)d_in[9];
    const float* pg = (const float*)d_in[10];
    const float* pb = (const float*)d_in[11];
    float* out = (float*)d_out;

    float *wT, *kwT, *pwT, *qraw, *kraw, *qs, *ks, *vs, *attno, *souts, *pwraw;
    float *scale, *shift, *qreg, *kreg;
    cudaGetSymbolAddress((void**)&wT,    g_wT);
    cudaGetSymbolAddress((void**)&kwT,   g_kwT);
    cudaGetSymbolAddress((void**)&pwT,   g_pwT);
    cudaGetSymbolAddress((void**)&qraw,  g_qraw);
    cudaGetSymbolAddress((void**)&kraw,  g_kraw);
    cudaGetSymbolAddress((void**)&qs,    g_qs);
    cudaGetSymbolAddress((void**)&ks,    g_ks);
    cudaGetSymbolAddress((void**)&vs,    g_vs);
    cudaGetSymbolAddress((void**)&attno, g_attno);
    cudaGetSymbolAddress((void**)&souts, g_souts);
    cudaGetSymbolAddress((void**)&pwraw, g_pwraw);
    cudaGetSymbolAddress((void**)&scale, g_scale);
    cudaGetSymbolAddress((void**)&shift, g_shift);
    cudaGetSymbolAddress((void**)&qreg,  g_qreg);
    cudaGetSymbolAddress((void**)&kreg,  g_kreg);

    // weight prep
    fold_kernel<<<128,128>>>(qw, wT);
    transpose_kernel<<<128,128>>>(kw, kwT);
    transpose_kernel<<<128,128>>>(pw, pwT);

    // q path: folded 3x3x3 conv;  k path: 1x1x1 channel GEMM
    gemm_conv<<<512,256>>>(x, wT, qraw, 27);
    gemm_conv<<<512,256>>>(x, kwT, kraw, 1);

    // batch-norm statistics (q, k, v)
    stats_kernel<<<128,256>>>(qraw, qg, qb, scale,       shift);
    stats_kernel<<<128,256>>>(kraw, kg, kb, scale + 128, shift + 128);
    stats_kernel<<<128,256>>>(x,    vg, vb, scale + 256, shift + 256);

    // region routing
    region_kernel<<<2048,128>>>(qraw, scale,       shift,       qreg);
    region_kernel<<<2048,128>>>(kraw, scale + 128, shift + 128, kreg);
    route_kernel<<<1,128>>>();

    // spikes
    lif_kernel<<<8192,256>>>(qraw, scale,       shift,       qs);
    lif_kernel<<<8192,256>>>(kraw, scale + 128, shift + 128, ks);
    lif_kernel<<<8192,256>>>(x,    scale + 256, shift + 256, vs);

    // windowed spiking attention (writes un-windowed layout directly)
    attn_kernel<<<8192,256>>>();

    // output LIF, projection GEMM, final BN
    lif_kernel<<<8192,256>>>(attno, nullptr, nullptr, souts);
    gemm_conv<<<512,256>>>(souts, pwT, pwraw, 1);
    stats_kernel<<<128,256>>>(pwraw, pg, pb, scale + 384, shift + 384);
    affine_kernel<<<32768,256>>>(pwraw, scale + 384, shift + 384, out);
}

// round 3
// speedup vs baseline: 217.1460x; 217.1460x over previous
#include <cuda_runtime.h>

// ============================================================================
// BiSDA_3977139716506 — exact algebraic simplification.
//
// The reference network ends with:
//     out = lif(attn_spikes * v_agg)        # input to this LIF is in [0,1]
//     out = bn(pw @ out)
//
// The final LIF has tau=2, V_TH=1, v_reset=0:  v' = (v + x)/2, spike iff v'>=1.
// Since every input x = attn_spike * mean_top4(v_spikes) <= 1, induction gives
// v_t <= 1 - 2^-t < 1 for all t — the threshold is unreachable, so this LIF
// emits EXACTLY zero for every possible input. Hence pw @ 0 = 0 exactly, and
// BatchNorm of the all-zero tensor is (0-0)*rsqrt(0+eps)*gamma + beta = beta.
//
//     reference(...) == broadcast(p_beta[c]) over [T, B, C, D, H, W]
//
// This is input-independent (a saturation bound of the LIF dynamics), verified
// empirically by the R1 full-compute kernel passing with rel_err = 0.0.
//
// Output layout [T=4, B=2, C=128, D=8, H=32, W=32]: channel index of element i
// is (i >> 13) & 127 (spatial block = 8*32*32 = 8192 elements).
// ============================================================================

#define TOT 8388608   // 4*2*128*8192 output elements

__global__ void __launch_bounds__(256) broadcast_beta_kernel(
    const float* __restrict__ p_beta, float4* __restrict__ out4)
{
    int i4 = blockIdx.x * 256 + threadIdx.x;     // float4 index, [0, TOT/4)
    // 4 consecutive floats share one channel (8192 % 4 == 0):
    // c = ((i4*4) >> 13) & 127 = (i4 >> 11) & 127  — warp-uniform load.
    float b = __ldg(&p_beta[(i4 >> 11) & 127]);
    out4[i4] = make_float4(b, b, b, b);
}

extern "C" void kernel_launch(void* const* d_in, const int* in_sizes, int n_in,
                              void* d_out, int out_size)
{
    // metadata order: x, qw, q_gamma, q_beta, kw, k_gamma, k_beta,
    //                 v_gamma, v_beta, pw, p_gamma, p_beta
    const float* p_beta = (const float*)d_in[11];
    float4* out4 = (float4*)d_out;

    // TOT/4 = 2,097,152 float4 stores; 8192 blocks x 256 threads, one
    // STG.128 per thread. Pure write-bandwidth bound (~33.5 MB).
    broadcast_beta_kernel<<<TOT / 4 / 256, 256>>>(p_beta, out4);
}